// round 11
// baseline (speedup 1.0000x reference)
#include <cuda_runtime.h>
#include <cuda_bf16.h>

// out[i,j] = log1p(max(0, Gauss9 ⊛ T)),  T[i,j] = Resize2x(img)[N-1-j, i] + 0.01*noise[i,j]
// Resize2x = jax.image.resize 'linear' (half-pixel centers, 2x => weights {0.25,0.75}, edge clamp)
// Blur: separable 9-tap sigma=1 Gaussian, numpy 'symmetric' padding on T.

#define NN 4096
#define MM 2048
#define TI 64
#define TJ 64
#define HALO 4
#define LI (TI + 2*HALO)   // 72
#define LJ (TJ + 2*HALO)   // 72
#define P1 73              // s1 pitch (odd -> conflict-free column access)
#define P2 76              // s2 pitch (mult of 4 -> aligned float4 loads)

__device__ __forceinline__ int symidx(int p) {
    p = (p < 0) ? (-1 - p) : p;
    return (p >= NN) ? (2 * NN - 1 - p) : p;
}

__global__ __launch_bounds__(256, 5)
void fused_aug_kernel(const float* __restrict__ img,
                      const float* __restrict__ noise,
                      float* __restrict__ out)
{
    __shared__ float s1[LI * P1];                 // T tile + halo (img part for interior)
    __shared__ __align__(16) float s2[TI * P2];   // vertically blurred

    const float KW[9] = {1.3383062e-4f, 4.4318616e-3f, 5.3991124e-2f,
                         2.4197145e-1f, 3.9894347e-1f, 2.4197145e-1f,
                         5.3991124e-2f, 4.4318616e-3f, 1.3383062e-4f};

    const int t  = threadIdx.x;
    const int bx = (int)blockIdx.x;
    const int by = (int)blockIdx.y;
    const int i0 = by * TI - HALO;
    const int j0 = bx * TJ - HALO;
    const bool edge = (bx == 0) | (by == 0) | (bx == 63) | (by == 63);

    if (!edge) {
        // ---- Phase A (interior): rotated 2x-resize, 2x2 outputs/thread ----
        for (int idx = t; idx < 35 * 36; idx += 256) {
            int c  = idx / 36;
            int m  = idx - c * 36;
            int jj = 2 * c + 1;
            int ii = 2 * m;
            int a  = 4095 - (j0 + jj);            // even
            int p  = a >> 1;
            const float* r0 = img + (size_t)(p - 1) * MM;
            const float* r1 = r0 + MM;
            int k = (i0 + ii) >> 1;
            float A0 = __ldg(&r0[k - 1]);
            float A1 = __ldg(&r0[k]);
            float A2 = __ldg(&r0[k + 1]);
            float B0 = __ldg(&r1[k - 1]);
            float B1 = __ldg(&r1[k]);
            float B2 = __ldg(&r1[k + 1]);
            float ea = fmaf(0.25f, A0, 0.75f * A1);
            float oa = fmaf(0.75f, A1, 0.25f * A2);
            float eb = fmaf(0.25f, B0, 0.75f * B1);
            float ob = fmaf(0.75f, B1, 0.25f * B2);
            float* s = s1 + ii * P1 + jj;
            s[0]      = fmaf(0.25f, ea, 0.75f * eb);
            s[1]      = fmaf(0.75f, ea, 0.25f * eb);
            s[P1]     = fmaf(0.25f, oa, 0.75f * ob);
            s[P1 + 1] = fmaf(0.75f, oa, 0.25f * ob);
        }
        // Leftover columns jj = 0 and jj = 71
        if (t < 72) {
            int col = t / 36;
            int m   = t - col * 36;
            int jj  = col ? (LJ - 1) : 0;
            int ii  = 2 * m;
            int a   = 4095 - (j0 + jj);
            int yf  = (a - 1) >> 1;
            float fy = (a & 1) ? 0.25f : 0.75f;
            const float* r0 = img + (size_t)yf * MM;
            const float* r1 = r0 + MM;
            int k = (i0 + ii) >> 1;
            float A0 = __ldg(&r0[k - 1]);
            float A1 = __ldg(&r0[k]);
            float A2 = __ldg(&r0[k + 1]);
            float B0 = __ldg(&r1[k - 1]);
            float B1 = __ldg(&r1[k]);
            float B2 = __ldg(&r1[k + 1]);
            float ea = fmaf(0.25f, A0, 0.75f * A1);
            float oa = fmaf(0.75f, A1, 0.25f * A2);
            float eb = fmaf(0.25f, B0, 0.75f * B1);
            float ob = fmaf(0.75f, B1, 0.25f * B2);
            s1[ii * P1 + jj]       = fmaf(fy, eb - ea, ea);
            s1[(ii + 1) * P1 + jj] = fmaf(fy, ob - oa, oa);
        }
        __syncthreads();

        // ---- Phase C (interior): noise fused into vertical blur, 16-row strips ----
        for (int idx = t; idx < 4 * LJ; idx += 256) {  // 288 tasks
            int g  = idx / LJ;
            int jj = idx - g * LJ;
            int ii = g * 16;
            const float* np = noise + (size_t)(i0 + ii) * NN + (j0 + jj);
            const float* sp = s1 + ii * P1 + jj;
            float a[16];
            #pragma unroll
            for (int r = 0; r < 16; r++)
                a[r] = fmaf(0.01f, __ldg(&np[(size_t)r * NN]), sp[r * P1]);
            #pragma unroll
            for (int r = 0; r < 8; r++) {
                float acc = 0.0f;
                #pragma unroll
                for (int d = 0; d < 9; d++) acc = fmaf(KW[d], a[r + d], acc);
                s2[(ii + r) * P2 + jj] = acc;
            }
            float b[8];
            #pragma unroll
            for (int r = 0; r < 8; r++)
                b[r] = fmaf(0.01f, __ldg(&np[(size_t)(16 + r) * NN]), sp[(16 + r) * P1]);
            #pragma unroll
            for (int r = 8; r < 16; r++) {
                float acc = 0.0f;
                #pragma unroll
                for (int d = 0; d < 9; d++) {
                    int s = r + d;
                    float x = (s < 16) ? a[s] : b[s - 16];
                    acc = fmaf(KW[d], x, acc);
                }
                s2[(ii + r) * P2 + jj] = acc;
            }
        }
    } else {
        // ---- Phase A (edge): symidx + clamps ----
        #pragma unroll 3
        for (int idx = t; idx < LI * LJ; idx += 256) {
            int jj = idx / LI;
            int ii = idx - jj * LI;
            int a  = NN - 1 - symidx(j0 + jj);
            int b  = symidx(i0 + ii);
            int yf = (a - 1) >> 1;
            int xf = (b - 1) >> 1;
            int y0 = max(yf, 0), y1 = min(yf + 1, MM - 1);
            int x0 = max(xf, 0), x1 = min(xf + 1, MM - 1);
            float fy = (a & 1) ? 0.25f : 0.75f;
            float fx = (b & 1) ? 0.25f : 0.75f;
            const float* r0 = img + (size_t)y0 * MM;
            const float* r1 = img + (size_t)y1 * MM;
            float v0 = __ldg(&r0[x0]);
            float v1 = __ldg(&r0[x1]);
            float w0 = __ldg(&r1[x0]);
            float w1 = __ldg(&r1[x1]);
            float h0 = fmaf(fx, v1 - v0, v0);
            float h1 = fmaf(fx, w1 - w0, w0);
            s1[ii * P1 + jj] = fmaf(fy, h1 - h0, h0);
        }
        __syncthreads();

        // ---- Phase B (edge): add noise with symidx ----
        #pragma unroll 3
        for (int idx = t; idx < LI * LJ; idx += 256) {
            int ii = idx / LJ;
            int jj = idx - ii * LJ;
            int gi = symidx(i0 + ii);
            int gj = symidx(j0 + jj);
            s1[ii * P1 + jj] += 0.01f * __ldg(&noise[(size_t)gi * NN + gj]);
        }
        __syncthreads();

        // ---- Phase C (edge): vertical blur, 16-row strips ----
        for (int idx = t; idx < 4 * LJ; idx += 256) {
            int g  = idx / LJ;
            int jj = idx - g * LJ;
            int ii = g * 16;
            const float* sp = s1 + ii * P1 + jj;
            float a[16];
            #pragma unroll
            for (int r = 0; r < 16; r++) a[r] = sp[r * P1];
            #pragma unroll
            for (int r = 0; r < 8; r++) {
                float acc = 0.0f;
                #pragma unroll
                for (int d = 0; d < 9; d++) acc = fmaf(KW[d], a[r + d], acc);
                s2[(ii + r) * P2 + jj] = acc;
            }
            float b[8];
            #pragma unroll
            for (int r = 0; r < 8; r++) b[r] = sp[(16 + r) * P1];
            #pragma unroll
            for (int r = 8; r < 16; r++) {
                float acc = 0.0f;
                #pragma unroll
                for (int d = 0; d < 9; d++) {
                    int s = r + d;
                    float x = (s < 16) ? a[s] : b[s - 16];
                    acc = fmaf(KW[d], x, acc);
                }
                s2[(ii + r) * P2 + jj] = acc;
            }
        }
    }
    __syncthreads();

    // ---- Phase D: horizontal blur + clip + fast log1p, 16 outputs/thread ----
    {
        const int oi0 = by * TI;
        const int oj0 = bx * TJ;
        int ii = t >> 2;                // 0..63
        int jj = (t & 3) * 16;          // 0,16,32,48
        const float* row = &s2[ii * P2 + jj];
        float4 c0 = *(const float4*)(row);
        float4 c1 = *(const float4*)(row + 4);
        float4 c2 = *(const float4*)(row + 8);
        float4 c3 = *(const float4*)(row + 12);
        float4 c4 = *(const float4*)(row + 16);
        float4 c5 = *(const float4*)(row + 20);
        float v[24] = {c0.x, c0.y, c0.z, c0.w,  c1.x, c1.y, c1.z, c1.w,
                       c2.x, c2.y, c2.z, c2.w,  c3.x, c3.y, c3.z, c3.w,
                       c4.x, c4.y, c4.z, c4.w,  c5.x, c5.y, c5.z, c5.w};
        float* dst = &out[(size_t)(oi0 + ii) * NN + (oj0 + jj)];
        #pragma unroll
        for (int q = 0; q < 4; q++) {
            float res[4];
            #pragma unroll
            for (int r = 0; r < 4; r++) {
                float acc = 0.0f;
                #pragma unroll
                for (int d = 0; d < 9; d++) acc = fmaf(KW[d], v[q * 4 + r + d], acc);
                res[r] = __logf(1.0f + fmaxf(acc, 0.0f));
            }
            *(float4*)(dst + q * 4) = make_float4(res[0], res[1], res[2], res[3]);
        }
    }
}

extern "C" void kernel_launch(void* const* d_in, const int* in_sizes, int n_in,
                              void* d_out, int out_size) {
    const float* img   = (const float*)d_in[0];   // (1,2048,2048) f32
    const float* noise = (const float*)d_in[1];   // (1,4096,4096) f32
    if (n_in >= 2 && in_sizes[0] > in_sizes[1]) {
        const float* tmp = img; img = noise; noise = tmp;
    }
    dim3 grid(NN / TJ, NN / TI);
    fused_aug_kernel<<<grid, 256>>>(img, noise, (float*)d_out);
}

// round 13
// speedup vs baseline: 1.5502x; 1.5502x over previous
#include <cuda_runtime.h>
#include <cuda_bf16.h>

// out[i,j] = log1p(max(0, Gauss9 ⊛ T)),  T[i,j] = Resize2x(img)[N-1-j, i] + 0.01*noise[i,j]
// Resize2x = jax.image.resize 'linear' (half-pixel centers, 2x => weights {0.25,0.75}, edge clamp)
// Blur: separable 9-tap sigma=1 Gaussian, numpy 'symmetric' padding on T.

#define NN 4096
#define MM 2048
#define TI 64
#define TJ 64
#define HALO 4
#define LI (TI + 2*HALO)   // 72
#define LJ (TJ + 2*HALO)   // 72
#define P1 73              // s1 pitch (odd -> conflict-free column access)
#define P2 76              // s2 pitch (mult of 4 -> aligned float4 loads)

#define KW0 1.3383062e-4f
#define KW1 4.4318616e-3f
#define KW2 5.3991124e-2f
#define KW3 2.4197145e-1f
#define KW4 3.9894347e-1f

__device__ __forceinline__ int symidx(int p) {
    p = (p < 0) ? (-1 - p) : p;
    return (p >= NN) ? (2 * NN - 1 - p) : p;
}

// Vertical 9-tap blur on an 8-row strip at (ii, jj), optionally fusing the noise add.
__device__ __forceinline__ void vstrip(const float* __restrict__ noise,
                                       const float* __restrict__ s1,
                                       float* __restrict__ s2,
                                       int i0, int j0, int ii, int jj, bool withNoise)
{
    const float KW[9] = {KW0, KW1, KW2, KW3, KW4, KW3, KW2, KW1, KW0};
    const float* sp = s1 + ii * P1 + jj;
    float v[16];
    if (withNoise) {
        const float* np = noise + (size_t)(i0 + ii) * NN + (j0 + jj);
        #pragma unroll
        for (int r = 0; r < 16; r++)
            v[r] = fmaf(0.01f, __ldg(&np[(size_t)r * NN]), sp[r * P1]);
    } else {
        #pragma unroll
        for (int r = 0; r < 16; r++) v[r] = sp[r * P1];
    }
    #pragma unroll
    for (int r = 0; r < 8; r++) {
        float acc = 0.0f;
        #pragma unroll
        for (int d = 0; d < 9; d++) acc = fmaf(KW[d], v[r + d], acc);
        s2[(ii + r) * P2 + jj] = acc;
    }
}

__global__ __launch_bounds__(256, 5)
void fused_aug_kernel(const float* __restrict__ img,
                      const float* __restrict__ noise,
                      float* __restrict__ out)
{
    __shared__ float s1[LI * P1];                 // T tile + halo (img part for interior)
    __shared__ __align__(16) float s2[TI * P2];   // vertically blurred

    const float KW[9] = {KW0, KW1, KW2, KW3, KW4, KW3, KW2, KW1, KW0};

    const int t  = threadIdx.x;
    const int bx = (int)blockIdx.x;
    const int by = (int)blockIdx.y;
    const int i0 = by * TI - HALO;
    const int j0 = bx * TJ - HALO;
    const bool edge = (bx == 0) | (by == 0) | (bx == 63) | (by == 63);

    if (!edge) {
        // ---- Phase A (interior): rotated 2x-resize, 2x2 outputs/thread ----
        for (int idx = t; idx < 35 * 36; idx += 256) {
            int c  = idx / 36;
            int m  = idx - c * 36;
            int jj = 2 * c + 1;
            int ii = 2 * m;
            int a  = 4095 - (j0 + jj);            // even
            int p  = a >> 1;
            const float* r0 = img + (size_t)(p - 1) * MM;
            const float* r1 = r0 + MM;
            int k = (i0 + ii) >> 1;
            float A0 = __ldg(&r0[k - 1]);
            float A1 = __ldg(&r0[k]);
            float A2 = __ldg(&r0[k + 1]);
            float B0 = __ldg(&r1[k - 1]);
            float B1 = __ldg(&r1[k]);
            float B2 = __ldg(&r1[k + 1]);
            float ea = fmaf(0.25f, A0, 0.75f * A1);
            float oa = fmaf(0.75f, A1, 0.25f * A2);
            float eb = fmaf(0.25f, B0, 0.75f * B1);
            float ob = fmaf(0.75f, B1, 0.25f * B2);
            float* s = s1 + ii * P1 + jj;
            s[0]      = fmaf(0.25f, ea, 0.75f * eb);
            s[1]      = fmaf(0.75f, ea, 0.25f * eb);
            s[P1]     = fmaf(0.25f, oa, 0.75f * ob);
            s[P1 + 1] = fmaf(0.75f, oa, 0.25f * ob);
        }
        // Leftover columns jj = 0 and jj = 71
        if (t < 72) {
            int col = t / 36;
            int m   = t - col * 36;
            int jj  = col ? (LJ - 1) : 0;
            int ii  = 2 * m;
            int a   = 4095 - (j0 + jj);
            int yf  = (a - 1) >> 1;
            float fy = (a & 1) ? 0.25f : 0.75f;
            const float* r0 = img + (size_t)yf * MM;
            const float* r1 = r0 + MM;
            int k = (i0 + ii) >> 1;
            float A0 = __ldg(&r0[k - 1]);
            float A1 = __ldg(&r0[k]);
            float A2 = __ldg(&r0[k + 1]);
            float B0 = __ldg(&r1[k - 1]);
            float B1 = __ldg(&r1[k]);
            float B2 = __ldg(&r1[k + 1]);
            float ea = fmaf(0.25f, A0, 0.75f * A1);
            float oa = fmaf(0.75f, A1, 0.25f * A2);
            float eb = fmaf(0.25f, B0, 0.75f * B1);
            float ob = fmaf(0.75f, B1, 0.25f * B2);
            s1[ii * P1 + jj]       = fmaf(fy, eb - ea, ea);
            s1[(ii + 1) * P1 + jj] = fmaf(fy, ob - oa, oa);
        }
        __syncthreads();

        // ---- Phase C (interior): noise fused into vertical blur, 8-row strips ----
        // 576 tasks: rounds 1-2 fully dense; tail of 64 spread lane-sparse over ALL warps.
        #pragma unroll
        for (int q = 0; q < 2; q++) {
            int idx = t + q * 256;
            int g  = idx / LJ;
            int jj = idx - g * LJ;
            vstrip(noise, s1, s2, i0, j0, g * 8, jj, true);
        }
        if ((t & 3) == 0) {
            int idx = 512 + (t >> 2);            // 512..575
            int g  = idx / LJ;                    // 7
            int jj = idx - g * LJ;                // 8..71
            vstrip(noise, s1, s2, i0, j0, g * 8, jj, true);
        }
    } else {
        // ---- Phase A (edge): symidx + clamps ----
        #pragma unroll 3
        for (int idx = t; idx < LI * LJ; idx += 256) {
            int jj = idx / LI;
            int ii = idx - jj * LI;
            int a  = NN - 1 - symidx(j0 + jj);
            int b  = symidx(i0 + ii);
            int yf = (a - 1) >> 1;
            int xf = (b - 1) >> 1;
            int y0 = max(yf, 0), y1 = min(yf + 1, MM - 1);
            int x0 = max(xf, 0), x1 = min(xf + 1, MM - 1);
            float fy = (a & 1) ? 0.25f : 0.75f;
            float fx = (b & 1) ? 0.25f : 0.75f;
            const float* r0 = img + (size_t)y0 * MM;
            const float* r1 = img + (size_t)y1 * MM;
            float v0 = __ldg(&r0[x0]);
            float v1 = __ldg(&r0[x1]);
            float w0 = __ldg(&r1[x0]);
            float w1 = __ldg(&r1[x1]);
            float h0 = fmaf(fx, v1 - v0, v0);
            float h1 = fmaf(fx, w1 - w0, w0);
            s1[ii * P1 + jj] = fmaf(fy, h1 - h0, h0);
        }
        __syncthreads();

        // ---- Phase B (edge): add noise with symidx ----
        #pragma unroll 3
        for (int idx = t; idx < LI * LJ; idx += 256) {
            int ii = idx / LJ;
            int jj = idx - ii * LJ;
            int gi = symidx(i0 + ii);
            int gj = symidx(j0 + jj);
            s1[ii * P1 + jj] += 0.01f * __ldg(&noise[(size_t)gi * NN + gj]);
        }
        __syncthreads();

        // ---- Phase C (edge): vertical blur, 8-row strips, same balanced schedule ----
        #pragma unroll
        for (int q = 0; q < 2; q++) {
            int idx = t + q * 256;
            int g  = idx / LJ;
            int jj = idx - g * LJ;
            vstrip(noise, s1, s2, i0, j0, g * 8, jj, false);
        }
        if ((t & 3) == 0) {
            int idx = 512 + (t >> 2);
            int g  = idx / LJ;
            int jj = idx - g * LJ;
            vstrip(noise, s1, s2, i0, j0, g * 8, jj, false);
        }
    }
    __syncthreads();

    // ---- Phase D: horizontal blur + clip + fast log1p, 8 outputs/thread ----
    // NOTE: 8 outputs need a 16-float window (r+d reaches 15) -> 4x float4 loads.
    const int oi0 = by * TI;
    const int oj0 = bx * TJ;
    #pragma unroll
    for (int q = 0; q < 2; q++) {                 // 512 tasks, 2 exact rounds
        int idx = t + q * 256;
        int ii = idx >> 3;
        int jj = (idx & 7) * 8;
        const float* row = &s2[ii * P2 + jj];
        float4 a0 = *(const float4*)(row);
        float4 a1 = *(const float4*)(row + 4);
        float4 a2 = *(const float4*)(row + 8);
        float4 a3 = *(const float4*)(row + 12);
        float v[16] = {a0.x, a0.y, a0.z, a0.w,  a1.x, a1.y, a1.z, a1.w,
                       a2.x, a2.y, a2.z, a2.w,  a3.x, a3.y, a3.z, a3.w};
        float res[8];
        #pragma unroll
        for (int r = 0; r < 8; r++) {
            float acc = 0.0f;
            #pragma unroll
            for (int d = 0; d < 9; d++) acc = fmaf(KW[d], v[r + d], acc);
            res[r] = __logf(1.0f + fmaxf(acc, 0.0f));
        }
        float* dst = &out[(size_t)(oi0 + ii) * NN + (oj0 + jj)];
        *(float4*)(dst)     = make_float4(res[0], res[1], res[2], res[3]);
        *(float4*)(dst + 4) = make_float4(res[4], res[5], res[6], res[7]);
    }
}

extern "C" void kernel_launch(void* const* d_in, const int* in_sizes, int n_in,
                              void* d_out, int out_size) {
    const float* img   = (const float*)d_in[0];   // (1,2048,2048) f32
    const float* noise = (const float*)d_in[1];   // (1,4096,4096) f32
    if (n_in >= 2 && in_sizes[0] > in_sizes[1]) {
        const float* tmp = img; img = noise; noise = tmp;
    }
    dim3 grid(NN / TJ, NN / TI);
    fused_aug_kernel<<<grid, 256>>>(img, noise, (float*)d_out);
}